// round 11
// baseline (speedup 1.0000x reference)
#include <cuda_runtime.h>
#include <cstdint>

#define DI __device__ __forceinline__

#define HID   256
#define KP1   320        // word dim 300 padded to 320
#define KP2   512
#define MLEAF 262144
#define VOCAB 50257
#define VPAD  50304      // 393 * 128
#define QMAX  16256.0f   // 127*128 + 0  (14-bit split range)

// ---- shared memory: 4-stage pipeline, K-chunk 64 int8 (64B rows) ----
#define SM_STAGE 1024
#define PL_SZ    8192                       // one plane: 128 rows x 64B
#define STG_SZ   (4 * PL_SZ)                // Ah, Al, Bh, Bl
#define SMEM_SZ  (SM_STAGE + 4 * STG_SZ)    // 132096 B -> 1 CTA/SM

// ---- static device scratch (no allocation allowed) ----
__device__ __align__(256) int8_t g_w1qh[256 * KP1];
__device__ __align__(256) int8_t g_w1ql[256 * KP1];
__device__ __align__(256) int8_t g_w2qh[256 * KP2];
__device__ __align__(256) int8_t g_w2ql[256 * KP2];
__device__ float    g_sb1[256];
__device__ float    g_sb2[256];
__device__ __align__(256) int8_t g_eqh[(size_t)VPAD * KP1];
__device__ __align__(256) int8_t g_eql[(size_t)VPAD * KP1];
__device__ float    g_saE[VPAD];
__device__ __align__(256) float  g_Tf[(size_t)VPAD * HID];     // T fp32
__device__ __align__(256) int8_t g_tqh[(size_t)VPAD * HID];
__device__ __align__(256) int8_t g_tql[(size_t)VPAD * HID];
__device__ float    g_saT[1];
__device__ unsigned g_gmax;
__device__ __align__(256) float  g_F[(size_t)(MLEAF / 2) * HID];       // level fp32 out
__device__ __align__(256) int8_t g_qh[(size_t)(MLEAF / 4) * KP2];
__device__ __align__(256) int8_t g_ql[(size_t)(MLEAF / 4) * KP2];
__device__ float    g_saA[MLEAF / 4];

// ---------------- PTX helpers (compute_103-safe ISA only) ----------------
DI uint32_t smem_u32(const void* p) {
    uint32_t a;
    asm("{ .reg .u64 t; cvta.to.shared.u64 t, %1; cvt.u32.u64 %0, t; }" : "=r"(a) : "l"(p));
    return a;
}

#define CPA16(dst, src) \
    asm volatile("cp.async.cg.shared.global [%0], [%1], 16;" :: "r"(dst), "l"(src))
#define CPA_COMMIT() \
    asm volatile("cp.async.commit_group;" ::: "memory")
#define CPA_WAIT(n) \
    asm volatile("cp.async.wait_group %0;" :: "n"(n) : "memory")

#define LDSM4(r0, r1, r2, r3, addr)                                            \
    asm volatile("ldmatrix.sync.aligned.m8n8.x4.shared.b16 {%0,%1,%2,%3}, [%4];" \
                 : "=r"(r0), "=r"(r1), "=r"(r2), "=r"(r3) : "r"(addr))

// int8 MMA: D(s32) += A(s8 16x32) * B(s8 32x8)
#define MMAI(d, a, b0, b1)                                                     \
    asm volatile("mma.sync.aligned.m16n8k32.row.col.s32.s8.s8.s32 "            \
                 "{%0,%1,%2,%3}, {%4,%5,%6,%7}, {%8,%9}, {%0,%1,%2,%3};"       \
                 : "+r"((d)[0]), "+r"((d)[1]), "+r"((d)[2]), "+r"((d)[3])      \
                 : "r"((a)[0]), "r"((a)[1]), "r"((a)[2]), "r"((a)[3]),         \
                   "r"(b0), "r"(b1))

// 64B-row swizzle (conflict-free for ldmatrix + 16B STS)
DI uint32_t sw64(uint32_t off) { return off ^ ((off >> 3) & 0x30); }

// 14-bit split quantization: v ~= del * (128*h + l), |h|<=127, |l|<=64
DI void quant14(float v, float inv, int8_t& h, int8_t& l) {
    int q = __float2int_rn(v * inv);
    q = max(-16256, min(16256, q));
    int hh = (q + 64) >> 7;
    int ll = q - (hh << 7);
    h = (int8_t)hh; l = (int8_t)ll;
}

DI float warpmax(float m) {
    #pragma unroll
    for (int o = 16; o; o >>= 1) m = fmaxf(m, __shfl_xor_sync(0xFFFFFFFFu, m, o));
    return m;
}

DI float blockmax256(float m) {   // blockDim.x == 256
    m = warpmax(m);
    __shared__ float red[8];
    __shared__ float bc;
    int w = threadIdx.x >> 5, l = threadIdx.x & 31;
    if (l == 0) red[w] = m;
    __syncthreads();
    if (threadIdx.x == 0) {
        float t = red[0];
        #pragma unroll
        for (int i = 1; i < 8; i++) t = fmaxf(t, red[i]);
        bc = t;
    }
    __syncthreads();
    return bc;
}

// ---------------- prep: quantize transposed weights ----------------
__global__ void prep_w_q(const float* __restrict__ W1, const float* __restrict__ W2) {
    int n = blockIdx.x;          // 0..255 -> W1t row n; 256..511 -> W2t row n-256
    int tid = threadIdx.x;
    if (n == 0 && tid == 0) g_gmax = 0u;
    const int K  = (n < 256) ? 300 : 512;
    const int KP = (n < 256) ? KP1 : KP2;
    float m = 0.0f;
    for (int k = tid; k < K; k += 256) {
        float v = (n < 256) ? W1[k * 256 + n] : W2[k * 256 + (n - 256)];
        m = fmaxf(m, fabsf(v));
    }
    m = blockmax256(m);
    float del = (m > 0.f) ? m / QMAX : 1.0f;
    float inv = (m > 0.f) ? QMAX / m : 0.0f;
    if (tid == 0) { if (n < 256) g_sb1[n] = del; else g_sb2[n - 256] = del; }
    for (int k = tid; k < KP; k += 256) {
        float v = 0.0f;
        if (k < K) v = (n < 256) ? W1[k * 256 + n] : W2[k * 256 + (n - 256)];
        int8_t h, l; quant14(v, inv, h, l);
        if (n < 256) { g_w1qh[n * KP1 + k] = h; g_w1ql[n * KP1 + k] = l; }
        else         { g_w2qh[(n - 256) * KP2 + k] = h; g_w2ql[(n - 256) * KP2 + k] = l; }
    }
}

// ---------------- prep: quantize embedding rows (padded) ----------------
__global__ void prep_emb_q(const float* __restrict__ E) {
    int v = blockIdx.x;          // 0..VPAD-1
    int tid = threadIdx.x;
    float m = 0.0f;
    if (v < VOCAB)
        for (int k = tid; k < 300; k += 256) m = fmaxf(m, fabsf(E[(size_t)v * 300 + k]));
    m = blockmax256(m);
    float del = (m > 0.f) ? m / QMAX : 1.0f;
    float inv = (m > 0.f) ? QMAX / m : 0.0f;
    if (tid == 0) g_saE[v] = del;
    for (int k = tid; k < KP1; k += 256) {
        float x = (v < VOCAB && k < 300) ? E[(size_t)v * 300 + k] : 0.0f;
        int8_t h, l; quant14(x, inv, h, l);
        g_eqh[(size_t)v * KP1 + k] = h;
        g_eql[(size_t)v * KP1 + k] = l;
    }
}

// ---------------- quantize T with the global (per-tensor) scale ----------------
__global__ void t_quant() {
    size_t i = (size_t)blockIdx.x * 512 + threadIdx.x;
    float gm = __uint_as_float(g_gmax);
    float del = (gm > 0.f) ? gm / QMAX : 1.0f;
    float inv = (gm > 0.f) ? QMAX / gm : 0.0f;
    if (i == 0) g_saT[0] = del;
    if (i < (size_t)VPAD * HID) {
        int8_t h, l; quant14(g_Tf[i], inv, h, l);
        g_tqh[i] = h; g_tql[i] = l;
    }
}

// ---------------- quantize level output per sibling-pair (next A rows) --------
__global__ void quant_pairs(const float* __restrict__ F,
                            int8_t* __restrict__ Qh, int8_t* __restrict__ Ql,
                            float* __restrict__ sa) {
    int p = blockIdx.x, t = threadIdx.x;   // 256 threads
    float v0 = F[(size_t)(2 * p) * HID + t];
    float v1 = F[(size_t)(2 * p + 1) * HID + t];
    float m = blockmax256(fmaxf(fabsf(v0), fabsf(v1)));
    float del = (m > 0.f) ? m / QMAX : 1.0f;
    float inv = (m > 0.f) ? QMAX / m : 0.0f;
    if (t == 0) sa[p] = del;
    int8_t h, l;
    quant14(v0, inv, h, l);
    Qh[(size_t)p * KP2 + t] = h;       Ql[(size_t)p * KP2 + t] = l;
    quant14(v1, inv, h, l);
    Qh[(size_t)p * KP2 + 256 + t] = h; Ql[(size_t)p * KP2 + 256 + t] = l;
}

// ---------------- int8 split GEMM: Of[128,128] = A[128,KPAD] @ B[128,KPAD]^T ----
// acc0 = sum ah*bh ; acc1 = sum (ah*bl + al*bh); V = da*db*(16384*acc0 + 128*acc1)+bias
// MODE 0: A row r at Aq[(m0+r)*KPAD]. MODE 1: row = concat(T[ids[2r]], T[ids[2r+1]]).
// GMAX 1: atomicMax |V| into g_gmax (for T per-tensor scale).
template <int MODE, int KPAD, int GMAX>
__global__ void __launch_bounds__(512, 1) gemm_q(
    const int* __restrict__ ids,
    const int8_t* __restrict__ Aqh, const int8_t* __restrict__ Aql,
    const int8_t* __restrict__ Bqh, const int8_t* __restrict__ Bql,
    const float* __restrict__ sa, const float* __restrict__ sb,
    const float* __restrict__ bias, float* __restrict__ Of,
    unsigned* __restrict__ gmax)
{
    extern __shared__ char smem[];
    const int tid = threadIdx.x, wid = tid >> 5, lid = tid & 31;
    const int m0 = blockIdx.x * 128, n0 = blockIdx.y * 128;
    const int wm = wid >> 2, wn = wid & 3;          // 4 x 4 warps, tile 32x32
    int* sids = (int*)smem;

    if (MODE == 1 && tid < 256) sids[tid] = ids[m0 * 2 + tid];
    __syncthreads();

    const uint32_t s_base = smem_u32(smem + SM_STAGE);
    const int NCH = KPAD / 64;

    // loader: 512 threads cover 128 rows x 4 16B-units, 4 planes each
    auto load_chunk = [&](int ch, int st) {
        const uint32_t stg = s_base + (uint32_t)st * STG_SZ;
        int r = tid >> 2, u = tid & 3;
        uint32_t d = sw64((uint32_t)(r * 64 + u * 16));
        size_t aoff;
        if (MODE == 1) {
            int id = sids[2 * r + (ch >> 2)];
            aoff = (size_t)id * HID + (size_t)((ch & 3) * 64 + u * 16);
        } else {
            aoff = (size_t)(m0 + r) * KPAD + (size_t)(ch * 64 + u * 16);
        }
        size_t boff = (size_t)(n0 + r) * KPAD + (size_t)(ch * 64 + u * 16);
        CPA16(stg + d,             (const char*)Aqh + aoff);
        CPA16(stg + PL_SZ + d,     (const char*)Aql + aoff);
        CPA16(stg + 2 * PL_SZ + d, (const char*)Bqh + boff);
        CPA16(stg + 3 * PL_SZ + d, (const char*)Bql + boff);
        CPA_COMMIT();
    };

    int acc0[2][4][4], acc1[2][4][4];
    #pragma unroll
    for (int i = 0; i < 2; i++)
        #pragma unroll
        for (int j = 0; j < 4; j++)
            #pragma unroll
            for (int c = 0; c < 4; c++) { acc0[i][j][c] = 0; acc1[i][j][c] = 0; }

    load_chunk(0, 0);
    if (NCH > 1) load_chunk(1, 1);
    if (NCH > 2) load_chunk(2, 2);

    for (int ch = 0; ch < NCH; ch++) {
        if (ch + 1 >= NCH)      { CPA_WAIT(0); }
        else if (ch + 2 >= NCH) { CPA_WAIT(1); }
        else                    { CPA_WAIT(2); }
        __syncthreads();
        if (ch + 3 < NCH) load_chunk(ch + 3, (ch + 3) & 3);

        const uint32_t stg = s_base + (uint32_t)(ch & 3) * STG_SZ;
        const uint32_t s_ah = stg, s_al = stg + PL_SZ;
        const uint32_t s_bh = stg + 2 * PL_SZ, s_bl = stg + 3 * PL_SZ;

        #pragma unroll
        for (int ks = 0; ks < 2; ks++) {      // two k32 steps per 64B chunk
            uint32_t a[2][4], bh[4][2], bl[4][2];

            #pragma unroll
            for (int i = 0; i < 2; i++) {     // A hi frags (16x32 int8 = 16x16 b16)
                int row = wm * 32 + i * 16 + (lid & 15);
                int cg  = ks * 2 + (lid >> 4);
                LDSM4(a[i][0], a[i][1], a[i][2], a[i][3],
                      s_ah + sw64(row * 64 + (cg << 4)));
            }
            #pragma unroll
            for (int p = 0; p < 2; p++) {     // B hi: 2 LDSM4 -> 4 n8 frags
                int row = wn * 32 + p * 16 + ((lid & 7) + ((lid >> 4) << 3));
                int cg  = ks * 2 + ((lid >> 3) & 1);
                LDSM4(bh[2 * p][0], bh[2 * p][1], bh[2 * p + 1][0], bh[2 * p + 1][1],
                      s_bh + sw64(row * 64 + (cg << 4)));
            }
            // pass 1: ah * bh -> acc0
            #pragma unroll
            for (int i = 0; i < 2; i++)
                #pragma unroll
                for (int j = 0; j < 4; j++)
                    MMAI(acc0[i][j], a[i], bh[j][0], bh[j][1]);

            #pragma unroll
            for (int p = 0; p < 2; p++) {     // B lo
                int row = wn * 32 + p * 16 + ((lid & 7) + ((lid >> 4) << 3));
                int cg  = ks * 2 + ((lid >> 3) & 1);
                LDSM4(bl[2 * p][0], bl[2 * p][1], bl[2 * p + 1][0], bl[2 * p + 1][1],
                      s_bl + sw64(row * 64 + (cg << 4)));
            }
            // pass 2: ah * bl -> acc1
            #pragma unroll
            for (int i = 0; i < 2; i++)
                #pragma unroll
                for (int j = 0; j < 4; j++)
                    MMAI(acc1[i][j], a[i], bl[j][0], bl[j][1]);

            #pragma unroll
            for (int i = 0; i < 2; i++) {     // A lo frags (reuse a regs)
                int row = wm * 32 + i * 16 + (lid & 15);
                int cg  = ks * 2 + (lid >> 4);
                LDSM4(a[i][0], a[i][1], a[i][2], a[i][3],
                      s_al + sw64(row * 64 + (cg << 4)));
            }
            // pass 3: al * bh -> acc1
            #pragma unroll
            for (int i = 0; i < 2; i++)
                #pragma unroll
                for (int j = 0; j < 4; j++)
                    MMAI(acc1[i][j], a[i], bh[j][0], bh[j][1]);
        }
    }

    // ---- epilogue: dequant + bias, fp32 store; optional global |max| ----
    float lmax = 0.0f;
    #pragma unroll
    for (int i = 0; i < 2; i++) {
        int r = m0 + wm * 32 + i * 16 + (lid >> 2);
        float da0 = (MODE == 1) ? sa[0] : sa[r];
        float da1 = (MODE == 1) ? sa[0] : sa[r + 8];
        #pragma unroll
        for (int j = 0; j < 4; j++) {
            int c = n0 + wn * 32 + j * 8 + 2 * (lid & 3);
            float s0 = sb[c], s1 = sb[c + 1];
            float b0 = bias[c], b1 = bias[c + 1];
            float v00 = da0 * s0 * (16384.f * (float)acc0[i][j][0] + 128.f * (float)acc1[i][j][0]) + b0;
            float v01 = da0 * s1 * (16384.f * (float)acc0[i][j][1] + 128.f * (float)acc1[i][j][1]) + b1;
            float v10 = da1 * s0 * (16384.f * (float)acc0[i][j][2] + 128.f * (float)acc1[i][j][2]) + b0;
            float v11 = da1 * s1 * (16384.f * (float)acc0[i][j][3] + 128.f * (float)acc1[i][j][3]) + b1;
            *(float2*)(Of + (size_t)r * HID + c)       = make_float2(v00, v01);
            *(float2*)(Of + (size_t)(r + 8) * HID + c) = make_float2(v10, v11);
            if (GMAX) lmax = fmaxf(fmaxf(fmaxf(fabsf(v00), fabsf(v01)),
                                         fmaxf(fabsf(v10), fabsf(v11))), lmax);
        }
    }
    if (GMAX) {
        lmax = warpmax(lmax);
        if (lid == 0) atomicMax(gmax, __float_as_uint(lmax));
    }
}

// ---------------- driver ----------------
extern "C" void kernel_launch(void* const* d_in, const int* in_sizes, int n_in,
                              void* d_out, int out_size) {
    const int*   ids = (const int*)d_in[0];
    const float* emb = (const float*)d_in[1];
    const float* W1  = (const float*)d_in[2];
    const float* b1  = (const float*)d_in[3];
    const float* W2  = (const float*)d_in[4];
    const float* b2  = (const float*)d_in[5];
    float* out = (float*)d_out;

    int8_t *w1h, *w1l, *w2h, *w2l, *eh, *el, *th, *tl, *qh, *ql;
    float *sb1, *sb2, *saE, *saT, *saA, *Tf, *F;
    unsigned* gmax;
    cudaGetSymbolAddress((void**)&w1h, g_w1qh);
    cudaGetSymbolAddress((void**)&w1l, g_w1ql);
    cudaGetSymbolAddress((void**)&w2h, g_w2qh);
    cudaGetSymbolAddress((void**)&w2l, g_w2ql);
    cudaGetSymbolAddress((void**)&sb1, g_sb1);
    cudaGetSymbolAddress((void**)&sb2, g_sb2);
    cudaGetSymbolAddress((void**)&eh,  g_eqh);
    cudaGetSymbolAddress((void**)&el,  g_eql);
    cudaGetSymbolAddress((void**)&saE, g_saE);
    cudaGetSymbolAddress((void**)&Tf,  g_Tf);
    cudaGetSymbolAddress((void**)&th,  g_tqh);
    cudaGetSymbolAddress((void**)&tl,  g_tql);
    cudaGetSymbolAddress((void**)&saT, g_saT);
    cudaGetSymbolAddress((void**)&gmax, g_gmax);
    cudaGetSymbolAddress((void**)&F,   g_F);
    cudaGetSymbolAddress((void**)&qh,  g_qh);
    cudaGetSymbolAddress((void**)&ql,  g_ql);
    cudaGetSymbolAddress((void**)&saA, g_saA);

    cudaFuncSetAttribute(gemm_q<0, KP1, 1>, cudaFuncAttributeMaxDynamicSharedMemorySize, SMEM_SZ);
    cudaFuncSetAttribute(gemm_q<1, KP2, 0>, cudaFuncAttributeMaxDynamicSharedMemorySize, SMEM_SZ);
    cudaFuncSetAttribute(gemm_q<0, KP2, 0>, cudaFuncAttributeMaxDynamicSharedMemorySize, SMEM_SZ);

    // quantize weights (transposed, padded) and embeddings; reset gmax
    prep_w_q<<<512, 256>>>(W1, W2);
    prep_emb_q<<<VPAD, 256>>>(emb);

    // T = E @ W1t + b1 over padded vocab -> Tf fp32 [VPAD,256], track |max|
    gemm_q<0, KP1, 1><<<dim3(VPAD / 128, 2), 512, SMEM_SZ>>>(
        nullptr, eh, el, w1h, w1l, saE, sb1, b1, Tf, gmax);
    // per-tensor quantize T
    t_quant<<<(int)(((size_t)VPAD * HID) / 512), 512>>>();

    // level 1: A rows = concat(T[ids[2r]], T[ids[2r+1]]) -> F fp32 [131072,256]
    gemm_q<1, KP2, 0><<<dim3((MLEAF / 2) / 128, 2), 512, SMEM_SZ>>>(
        ids, th, tl, w2h, w2l, saT, sb2, b2, F, nullptr);

    // levels 2+: quantize pairs, then GEMM; final level writes d_out
    int rows = MLEAF / 2;
    while (rows > 256) {
        int pairs = rows / 2;
        quant_pairs<<<pairs, 256>>>(F, qh, ql, saA);
        float* dst = (pairs == 256) ? out : F;
        gemm_q<0, KP2, 0><<<dim3(pairs / 128, 2), 512, SMEM_SZ>>>(
            nullptr, qh, ql, w2h, w2l, saA, sb2, b2, dst, nullptr);
        rows = pairs;
    }
}

// round 14
// speedup vs baseline: 6.0595x; 6.0595x over previous
#include <cuda_runtime.h>
#include <cuda_bf16.h>
#include <cstdint>

#define DI __device__ __forceinline__

#define HID   256
#define KP1   320        // word dim 300 padded to 320
#define KF    1024       // fused 2-level K
#define MLEAF 262144
#define VOCAB 50257
#define VPAD  50304      // 393 * 128
#define TPB   256

// ---- shared memory: 3-stage pipeline, K-chunk 32 bf16 (64B rows) ----
#define SM_IDS   0                          // up to 512 ints
#define SM_STAGE 2048
#define STG_SZ   32768
#define PL_SZ    8192
#define SMEM_SZ  (SM_STAGE + 3 * STG_SZ)    // 100352 B -> 2 CTAs/SM

// ---- static device scratch (no allocation allowed) ----
__device__ __align__(256) __nv_bfloat16 g_w1h[HID * KP1];
__device__ __align__(256) __nv_bfloat16 g_w1l[HID * KP1];
__device__ __align__(256) __nv_bfloat16 g_w4h[HID * KF];    // fused weight [256][1024]
__device__ __align__(256) __nv_bfloat16 g_w4l[HID * KF];
__device__ float g_b4[HID];
__device__ __align__(256) __nv_bfloat16 g_eh[(size_t)VPAD * KP1];
__device__ __align__(256) __nv_bfloat16 g_el[(size_t)VPAD * KP1];
__device__ __align__(256) __nv_bfloat16 g_Th[(size_t)VPAD * HID];   // T = E*W1+b1
__device__ __align__(256) __nv_bfloat16 g_Tl[(size_t)VPAD * HID];
__device__ __align__(256) __nv_bfloat16 g_p0h[(size_t)(MLEAF / 4) * HID];
__device__ __align__(256) __nv_bfloat16 g_p0l[(size_t)(MLEAF / 4) * HID];
__device__ __align__(256) __nv_bfloat16 g_p1h[(size_t)(MLEAF / 16) * HID];
__device__ __align__(256) __nv_bfloat16 g_p1l[(size_t)(MLEAF / 16) * HID];

// ---------------- PTX helpers (compute_103-safe ISA only) ----------------
DI uint32_t smem_u32(const void* p) {
    uint32_t a;
    asm("{ .reg .u64 t; cvta.to.shared.u64 t, %1; cvt.u32.u64 %0, t; }" : "=r"(a) : "l"(p));
    return a;
}

#define CPA16(dst, src) \
    asm volatile("cp.async.cg.shared.global [%0], [%1], 16;" :: "r"(dst), "l"(src))
#define CPA_COMMIT() \
    asm volatile("cp.async.commit_group;" ::: "memory")
#define CPA_WAIT(n) \
    asm volatile("cp.async.wait_group %0;" :: "n"(n) : "memory")

#define LDSM4(r0, r1, r2, r3, addr)                                            \
    asm volatile("ldmatrix.sync.aligned.m8n8.x4.shared.b16 {%0,%1,%2,%3}, [%4];" \
                 : "=r"(r0), "=r"(r1), "=r"(r2), "=r"(r3) : "r"(addr))

#define MMA16816(d, a, b0, b1)                                                 \
    asm volatile("mma.sync.aligned.m16n8k16.row.col.f32.bf16.bf16.f32 "        \
                 "{%0,%1,%2,%3}, {%4,%5,%6,%7}, {%8,%9}, {%0,%1,%2,%3};"       \
                 : "+f"((d)[0]), "+f"((d)[1]), "+f"((d)[2]), "+f"((d)[3])      \
                 : "r"((a)[0]), "r"((a)[1]), "r"((a)[2]), "r"((a)[3]),         \
                   "r"(b0), "r"(b1))

DI void split2(float v, __nv_bfloat16& h, __nv_bfloat16& l) {
    h = __float2bfloat16(v);
    l = __float2bfloat16(v - __bfloat162float(h));
}

// 64B-row swizzle: XOR col16 bits[4:5] with row byte bits[7:8]
DI uint32_t sw64(uint32_t off) { return off ^ ((off >> 3) & 0x30); }

// ---------------- prep: split W1 transposed + padded ----------------
__global__ void prep_w1(const float* __restrict__ W1) {
    int i = blockIdx.x * blockDim.x + threadIdx.x;
    if (i >= HID * KP1) return;
    int n = i / KP1, k = i % KP1;
    float v = (k < 300) ? W1[k * HID + n] : 0.0f;
    __nv_bfloat16 h, l;
    split2(v, h, l);
    g_w1h[i] = h; g_w1l[i] = l;
}

// ---------------- prep: fused 2-level weight W4 = [[W2*W2top];[W2*W2bot]] ------
// block k<1024: W4 row k (fp32 inner product over 256), split-stored transposed.
// block 1024: b4[n] = b2[n] + sum_j b2[j]*(W2[j][n] + W2[256+j][n]).
__global__ void prep_w4(const float* __restrict__ W2, const float* __restrict__ b2) {
    int k = blockIdx.x, n = threadIdx.x;
    if (k < KF) {
        const float* wrow = W2 + (size_t)((k < 512) ? k : k - 512) * HID;
        const float* wcol = W2 + (size_t)((k < 512) ? 0 : 256) * HID + n;
        float s = 0.f;
        for (int j = 0; j < 256; j++)
            s += wrow[j] * wcol[(size_t)j * HID];
        __nv_bfloat16 h, l;
        split2(s, h, l);
        g_w4h[n * KF + k] = h;
        g_w4l[n * KF + k] = l;
    } else {
        float s = b2[n];
        for (int j = 0; j < 256; j++)
            s += b2[j] * (W2[(size_t)j * HID + n] + W2[(size_t)(256 + j) * HID + n]);
        g_b4[n] = s;
    }
}

// ---------------- prep: split embedding table (padded rows/cols) ----------------
__global__ void prep_emb(const float* __restrict__ E) {
    size_t i = (size_t)blockIdx.x * blockDim.x + threadIdx.x;
    if (i >= (size_t)VPAD * KP1) return;
    int v = (int)(i / KP1), k = (int)(i % KP1);
    float x = (v < VOCAB && k < 300) ? E[(size_t)v * 300 + k] : 0.0f;
    __nv_bfloat16 h, l;
    split2(x, h, l);
    g_eh[i] = h; g_el[i] = l;
}

// ---------------- GEMM: Out[128,128] = A[128,KPAD] @ Wt[128,KPAD]^T + bias ----
// Split-bf16 3-MMA (hh + hl + lh), 3-stage cp.async pipeline, K-chunk 32.
// MODE 0: A row r = Ah/Al[(m0+r)*KPAD + k]                    (direct view)
// MODE 1: A row r = concat(T[ids[4r]],..,T[ids[4r+3]]), KPAD=1024, T stride HID
template <int MODE, int KPAD, int FINAL>
__global__ void __launch_bounds__(TPB, 2) gemm_kernel(
    const int* __restrict__ ids,
    const __nv_bfloat16* __restrict__ Ah, const __nv_bfloat16* __restrict__ Al,
    const __nv_bfloat16* __restrict__ Bh, const __nv_bfloat16* __restrict__ Bl,
    const float* __restrict__ bias,
    __nv_bfloat16* __restrict__ Oh, __nv_bfloat16* __restrict__ Ol,
    float* __restrict__ Of)
{
    extern __shared__ char smem[];
    const int tid = threadIdx.x, wid = tid >> 5, lid = tid & 31;
    const int m0 = blockIdx.x * 128, n0 = blockIdx.y * 128;
    const int wm = wid >> 2, wn = wid & 3;              // 2 x 4 warp grid
    int* sids = (int*)smem;

    if (MODE == 1) {
        sids[tid] = ids[m0 * 4 + tid];
        sids[tid + 256] = ids[m0 * 4 + 256 + tid];
    }
    __syncthreads();

    const uint32_t s_base = smem_u32(smem + SM_STAGE);
    const int NCH = KPAD / 32;

    // loader: all cp.async for chunk ch into stage st
    auto load_chunk = [&](int ch, int st) {
        const uint32_t stg = s_base + (uint32_t)st * STG_SZ;
        #pragma unroll
        for (int v = tid; v < 512; v += TPB) {           // A hi + A lo
            int r = v >> 2, u = v & 3;
            size_t off;
            if (MODE == 1) {
                int id = sids[4 * r + (ch >> 3)];        // 8 chunks per T row
                off = (size_t)id * (HID * 2) + (size_t)((ch & 7) * 64 + u * 16);
            } else {
                off = (size_t)(m0 + r) * (KPAD * 2) + (size_t)(ch * 64 + u * 16);
            }
            uint32_t d = sw64((uint32_t)(r * 64 + u * 16));
            CPA16(stg + d,         (const char*)Ah + off);
            CPA16(stg + PL_SZ + d, (const char*)Al + off);
        }
        #pragma unroll
        for (int v = tid; v < 512; v += TPB) {           // B hi + B lo
            int r = v >> 2, u = v & 3;
            size_t off = (size_t)(n0 + r) * (KPAD * 2) + (size_t)(ch * 64 + u * 16);
            uint32_t d = sw64((uint32_t)(r * 64 + u * 16));
            CPA16(stg + 2 * PL_SZ + d, (const char*)Bh + off);
            CPA16(stg + 3 * PL_SZ + d, (const char*)Bl + off);
        }
        CPA_COMMIT();
    };

    float acc[4][4][4];
    #pragma unroll
    for (int i = 0; i < 4; i++)
        #pragma unroll
        for (int j = 0; j < 4; j++)
            #pragma unroll
            for (int c = 0; c < 4; c++) acc[i][j][c] = 0.0f;

    load_chunk(0, 0);
    load_chunk(1, 1);

    for (int ch = 0; ch < NCH; ch++) {
        if (ch == NCH - 1) { CPA_WAIT(0); } else { CPA_WAIT(1); }
        __syncthreads();   // chunk ch ready; stage (ch+2)%3's old data fully consumed
        if (ch + 2 < NCH) load_chunk(ch + 2, (ch + 2) % 3);

        const uint32_t stg = s_base + (uint32_t)(ch % 3) * STG_SZ;
        const uint32_t s_ahi = stg, s_alo = stg + PL_SZ;
        const uint32_t s_bhi = stg + 2 * PL_SZ, s_blo = stg + 3 * PL_SZ;

        #pragma unroll
        for (int ks = 0; ks < 2; ks++) {
            uint32_t a[4][4], bh[4][2], bl[4][2];

            #pragma unroll
            for (int i = 0; i < 4; i++) {
                int row = wm * 64 + i * 16 + (lid & 15);
                int col = ks * 2 + (lid >> 4);
                LDSM4(a[i][0], a[i][1], a[i][2], a[i][3],
                      s_ahi + sw64(row * 64 + (col << 4)));
            }
            #pragma unroll
            for (int p = 0; p < 2; p++) {
                int row = wn * 32 + p * 16 + ((lid & 7) + ((lid >> 4) << 3));
                int col = ks * 2 + ((lid >> 3) & 1);
                LDSM4(bh[2 * p][0], bh[2 * p][1], bh[2 * p + 1][0], bh[2 * p + 1][1],
                      s_bhi + sw64(row * 64 + (col << 4)));
            }
            // pass 1: A_hi x B_hi
            #pragma unroll
            for (int i = 0; i < 4; i++)
                #pragma unroll
                for (int j = 0; j < 4; j++)
                    MMA16816(acc[i][j], a[i], bh[j][0], bh[j][1]);

            #pragma unroll
            for (int p = 0; p < 2; p++) {
                int row = wn * 32 + p * 16 + ((lid & 7) + ((lid >> 4) << 3));
                int col = ks * 2 + ((lid >> 3) & 1);
                LDSM4(bl[2 * p][0], bl[2 * p][1], bl[2 * p + 1][0], bl[2 * p + 1][1],
                      s_blo + sw64(row * 64 + (col << 4)));
            }
            // pass 2: A_hi x B_lo
            #pragma unroll
            for (int i = 0; i < 4; i++)
                #pragma unroll
                for (int j = 0; j < 4; j++)
                    MMA16816(acc[i][j], a[i], bl[j][0], bl[j][1]);

            #pragma unroll
            for (int i = 0; i < 4; i++) {
                int row = wm * 64 + i * 16 + (lid & 15);
                int col = ks * 2 + (lid >> 4);
                LDSM4(a[i][0], a[i][1], a[i][2], a[i][3],
                      s_alo + sw64(row * 64 + (col << 4)));
            }
            // pass 3: A_lo x B_hi
            #pragma unroll
            for (int i = 0; i < 4; i++)
                #pragma unroll
                for (int j = 0; j < 4; j++)
                    MMA16816(acc[i][j], a[i], bh[j][0], bh[j][1]);
        }
    }

    // ---- epilogue: +bias, write fp32 (final) or split bf16 planes ----
    #pragma unroll
    for (int i = 0; i < 4; i++) {
        int r0 = m0 + wm * 64 + i * 16 + (lid >> 2);
        #pragma unroll
        for (int j = 0; j < 4; j++) {
            int gc = n0 + wn * 32 + j * 8 + 2 * (lid & 3);
            float b0 = bias[gc], b1 = bias[gc + 1];
            float v00 = acc[i][j][0] + b0, v01 = acc[i][j][1] + b1;
            float v10 = acc[i][j][2] + b0, v11 = acc[i][j][3] + b1;
            if (FINAL) {
                *(float2*)(Of + (size_t)r0 * HID + gc)        = make_float2(v00, v01);
                *(float2*)(Of + (size_t)(r0 + 8) * HID + gc)  = make_float2(v10, v11);
            } else {
                __nv_bfloat16 h0, l0, h1, l1;
                split2(v00, h0, l0); split2(v01, h1, l1);
                union { __nv_bfloat16 b[2]; uint32_t u; } ph, pl;
                ph.b[0] = h0; ph.b[1] = h1; pl.b[0] = l0; pl.b[1] = l1;
                *(uint32_t*)(Oh + (size_t)r0 * HID + gc) = ph.u;
                *(uint32_t*)(Ol + (size_t)r0 * HID + gc) = pl.u;
                split2(v10, h0, l0); split2(v11, h1, l1);
                ph.b[0] = h0; ph.b[1] = h1; pl.b[0] = l0; pl.b[1] = l1;
                *(uint32_t*)(Oh + (size_t)(r0 + 8) * HID + gc) = ph.u;
                *(uint32_t*)(Ol + (size_t)(r0 + 8) * HID + gc) = pl.u;
            }
        }
    }
}

// ---------------- driver ----------------
extern "C" void kernel_launch(void* const* d_in, const int* in_sizes, int n_in,
                              void* d_out, int out_size) {
    const int*   ids = (const int*)d_in[0];
    const float* emb = (const float*)d_in[1];
    const float* W1  = (const float*)d_in[2];
    const float* b1  = (const float*)d_in[3];
    const float* W2  = (const float*)d_in[4];
    const float* b2  = (const float*)d_in[5];
    float* out = (float*)d_out;

    __nv_bfloat16 *w1h, *w1l, *w4h, *w4l, *eh, *el, *th, *tl, *p0h, *p0l, *p1h, *p1l;
    float* b4;
    cudaGetSymbolAddress((void**)&w1h, g_w1h);
    cudaGetSymbolAddress((void**)&w1l, g_w1l);
    cudaGetSymbolAddress((void**)&w4h, g_w4h);
    cudaGetSymbolAddress((void**)&w4l, g_w4l);
    cudaGetSymbolAddress((void**)&b4,  g_b4);
    cudaGetSymbolAddress((void**)&eh,  g_eh);
    cudaGetSymbolAddress((void**)&el,  g_el);
    cudaGetSymbolAddress((void**)&th,  g_Th);
    cudaGetSymbolAddress((void**)&tl,  g_Tl);
    cudaGetSymbolAddress((void**)&p0h, g_p0h);
    cudaGetSymbolAddress((void**)&p0l, g_p0l);
    cudaGetSymbolAddress((void**)&p1h, g_p1h);
    cudaGetSymbolAddress((void**)&p1l, g_p1l);

    cudaFuncSetAttribute(gemm_kernel<0, KP1, 0>, cudaFuncAttributeMaxDynamicSharedMemorySize, SMEM_SZ);
    cudaFuncSetAttribute(gemm_kernel<1, KF, 0>,  cudaFuncAttributeMaxDynamicSharedMemorySize, SMEM_SZ);
    cudaFuncSetAttribute(gemm_kernel<0, KF, 0>,  cudaFuncAttributeMaxDynamicSharedMemorySize, SMEM_SZ);
    cudaFuncSetAttribute(gemm_kernel<0, KF, 1>,  cudaFuncAttributeMaxDynamicSharedMemorySize, SMEM_SZ);

    prep_w1<<<(HID * KP1 + 255) / 256, 256>>>(W1);
    prep_w4<<<KF + 1, 256>>>(W2, b2);
    {
        size_t n = (size_t)VPAD * KP1;
        prep_emb<<<(int)((n + 255) / 256), 256>>>(emb);
    }

    // T = E @ W1t + b1 over padded vocab -> split planes [VPAD, 256]
    gemm_kernel<0, KP1, 0><<<dim3(VPAD / 128, 2), TPB, SMEM_SZ>>>(
        nullptr, eh, el, w1h, w1l, b1, th, tl, nullptr);

    // levels 1+2 fused: A row r = concat T[ids[4r..4r+3]] -> p0 [65536, 256]
    gemm_kernel<1, KF, 0><<<dim3((MLEAF / 4) / 128, 2), TPB, SMEM_SZ>>>(
        ids, th, tl, w4h, w4l, b4, p0h, p0l, nullptr);

    // levels 3+4: view p0 [65536,256] as [16384,1024] -> p1 [16384, 256]
    gemm_kernel<0, KF, 0><<<dim3((MLEAF / 16) / 128, 2), TPB, SMEM_SZ>>>(
        nullptr, p0h, p0l, w4h, w4l, b4, p1h, p1l, nullptr);

    // levels 5+6: [16384,256] -> [4096,1024] -> p0 [4096, 256]
    gemm_kernel<0, KF, 0><<<dim3(4096 / 128, 2), TPB, SMEM_SZ>>>(
        nullptr, p1h, p1l, w4h, w4l, b4, p0h, p0l, nullptr);

    // levels 7+8: [4096,256] -> [1024,1024] -> p1 [1024, 256]
    gemm_kernel<0, KF, 0><<<dim3(1024 / 128, 2), TPB, SMEM_SZ>>>(
        nullptr, p0h, p0l, w4h, w4l, b4, p1h, p1l, nullptr);

    // levels 9+10: [1024,256] -> [256,1024] -> out fp32 [256, 256]
    gemm_kernel<0, KF, 1><<<dim3(256 / 128, 2), TPB, SMEM_SZ>>>(
        nullptr, p1h, p1l, w4h, w4l, b4, nullptr, nullptr, out);
}